// round 2
// baseline (speedup 1.0000x reference)
#include <cuda_runtime.h>
#include <cuda_bf16.h>
#include <math.h>
#include <float.h>

// Problem constants
#define B_   8
#define S_   1024
#define IDIM 1024
#define ODIM 1024
#define H_   16
#define HD_  64
#define CN   3072           // K | Q | V columns in scratch
#define M_   (B_ * S_)      // 8192

// Scratch: C[row][0:1024]=K=X@Wv+bv, [1024:2048]=Q, [2048:3072]=V (both from Wc,bc)
__device__ float g_C[(size_t)M_ * CN];
// Partial column sums of V: 4 partials x (B*ODIM)
__device__ float g_vsum[4 * B_ * ODIM];

// ---------------------------------------------------------------------------
// Fused GEMM: C[8192 x 3072] = X[8192 x 1024] @ [Wv | Wc] + [bv | bc]
// 128x128x8 tiles, 256 threads, 8x8 microtile, packed fma.rn.f32x2
// ---------------------------------------------------------------------------
__device__ __forceinline__ unsigned long long pack_dup(float b) {
    unsigned long long r;
    asm("mov.b64 %0, {%1, %1};" : "=l"(r) : "f"(b));
    return r;
}
__device__ __forceinline__ void fma2(unsigned long long& acc,
                                     unsigned long long a, unsigned long long b) {
    asm("fma.rn.f32x2 %0, %1, %2, %0;" : "+l"(acc) : "l"(a), "l"(b));
}
__device__ __forceinline__ void unpack2(unsigned long long v, float& lo, float& hi) {
    asm("mov.b64 {%0, %1}, %2;" : "=f"(lo), "=f"(hi) : "l"(v));
}

__global__ void __launch_bounds__(256, 2) gemm_kernel(
    const float* __restrict__ X,
    const float* __restrict__ Wc, const float* __restrict__ bc,
    const float* __restrict__ Wv, const float* __restrict__ bv)
{
    const int n0 = blockIdx.x * 128;
    const int m0 = blockIdx.y * 128;

    const float* Wp; int ws; const float* bp;
    if (n0 < 1024) { Wp = Wv; ws = 1024; bp = bv + n0; Wp += n0; }
    else           { Wp = Wc; ws = 2048; bp = bc + (n0 - 1024); Wp += (n0 - 1024); }

    __shared__ __align__(16) float As[8][128];   // [k][m] transposed
    __shared__ __align__(16) float Bs[8][128];   // [k][n]

    const int t  = threadIdx.x;
    const int tx = t & 15;
    const int ty = t >> 4;

    // global A load: row = t>>1 (0..127), cols ac..ac+3 (ac in {0,4})
    const int arow = t >> 1;
    const int ac   = (t & 1) * 4;
    // global B load: row = t>>5 (0..7), cols bcol..bcol+3
    const int brow = t >> 5;
    const int bcol = (t & 31) * 4;

    const float* Ag = X + (size_t)(m0 + arow) * IDIM + ac;
    const float* Bg = Wp + (size_t)brow * ws + bcol;

    unsigned long long acc[4][8];
#pragma unroll
    for (int p = 0; p < 4; ++p)
#pragma unroll
        for (int n = 0; n < 8; ++n) acc[p][n] = 0ULL;   // {0.f, 0.f}

    float4 aReg = *(const float4*)Ag;
    float4 bReg = *(const float4*)Bg;

    for (int kt = 0; kt < 128; ++kt) {
        As[ac + 0][arow] = aReg.x;
        As[ac + 1][arow] = aReg.y;
        As[ac + 2][arow] = aReg.z;
        As[ac + 3][arow] = aReg.w;
        *(float4*)&Bs[brow][bcol] = bReg;
        __syncthreads();

        if (kt < 127) {
            Ag += 8;
            Bg += (size_t)8 * ws;
            aReg = *(const float4*)Ag;
            bReg = *(const float4*)Bg;
        }

#pragma unroll
        for (int kk = 0; kk < 8; ++kk) {
            // m-pairs, pack-free (As is [k][m], pairs adjacent)
            ulonglong2 a01 = *(const ulonglong2*)&As[kk][ty * 4];
            ulonglong2 a23 = *(const ulonglong2*)&As[kk][64 + ty * 4];
            unsigned long long am[4] = { a01.x, a01.y, a23.x, a23.y };
            // b values (conflict-free float4 loads), duplicated into pairs
            float4 bf0 = *(const float4*)&Bs[kk][tx * 4];
            float4 bf1 = *(const float4*)&Bs[kk][64 + tx * 4];
            unsigned long long bb[8];
            bb[0] = pack_dup(bf0.x); bb[1] = pack_dup(bf0.y);
            bb[2] = pack_dup(bf0.z); bb[3] = pack_dup(bf0.w);
            bb[4] = pack_dup(bf1.x); bb[5] = pack_dup(bf1.y);
            bb[6] = pack_dup(bf1.z); bb[7] = pack_dup(bf1.w);
#pragma unroll
            for (int p = 0; p < 4; ++p)
#pragma unroll
                for (int n = 0; n < 8; ++n)
                    fma2(acc[p][n], am[p], bb[n]);
        }
        __syncthreads();
    }

    // epilogue: unpack, add bias, store
    float bias[8];
#pragma unroll
    for (int c = 0; c < 4; ++c) {
        bias[c]     = bp[tx * 4 + c];
        bias[4 + c] = bp[64 + tx * 4 + c];
    }

#pragma unroll
    for (int p = 0; p < 4; ++p) {
        const int rbase = ty * 4 + ((p & 1) ? 2 : 0) + ((p & 2) ? 64 : 0);
        float lo[8], hi[8];
#pragma unroll
        for (int n = 0; n < 8; ++n) unpack2(acc[p][n], lo[n], hi[n]);

        float* out0 = g_C + (size_t)(m0 + rbase) * CN + n0;
        float* out1 = out0 + CN;
        float4 v;
        v.x = lo[0] + bias[0]; v.y = lo[1] + bias[1];
        v.z = lo[2] + bias[2]; v.w = lo[3] + bias[3];
        *(float4*)(out0 + tx * 4) = v;
        v.x = lo[4] + bias[4]; v.y = lo[5] + bias[5];
        v.z = lo[6] + bias[6]; v.w = lo[7] + bias[7];
        *(float4*)(out0 + 64 + tx * 4) = v;
        v.x = hi[0] + bias[0]; v.y = hi[1] + bias[1];
        v.z = hi[2] + bias[2]; v.w = hi[3] + bias[3];
        *(float4*)(out1 + tx * 4) = v;
        v.x = hi[4] + bias[4]; v.y = hi[5] + bias[5];
        v.z = hi[6] + bias[6]; v.w = hi[7] + bias[7];
        *(float4*)(out1 + 64 + tx * 4) = v;
    }
}

// ---------------------------------------------------------------------------
// Partial column sums of V (for the rare all-masked-window uniform fallback)
// grid (64, 4), 128 threads
// ---------------------------------------------------------------------------
__global__ void vsum_kernel()
{
    const int col = (blockIdx.x & 7) * 128 + threadIdx.x;     // 0..1023
    const int b   = blockIdx.x >> 3;
    const int s0  = blockIdx.y * 256;
    const float* base = g_C + (size_t)(b * S_ + s0) * CN + 2048 + col;
    float s = 0.0f;
#pragma unroll 8
    for (int k = 0; k < 256; ++k) s += base[(size_t)k * CN];
    g_vsum[blockIdx.y * (B_ * ODIM) + b * ODIM + col] = s;
}

// ---------------------------------------------------------------------------
// Local attention: one warp per (b, h, i) row.
// scores[i][j] = (k_i . q_j) / 8 for |i-j|<=7, masked by mask[b][j];
// softmax over j; w row written densely (zeros outside window);
// updated_m = m_feats + w @ v  (fused).
// ---------------------------------------------------------------------------
__global__ void __launch_bounds__(256) attn_kernel(
    const float* __restrict__ m_feats, const int* __restrict__ mask,
    float* __restrict__ out_um, float* __restrict__ out_w)
{
    __shared__ float sk[8][64];
    __shared__ float sw[8][16];

    const int wid = threadIdx.x >> 5;
    const int l   = threadIdx.x & 31;
    const int row = blockIdx.x * 8 + wid;      // (b*H + h)*S + i
    const int b   = row >> 14;
    const int h   = (row >> 10) & 15;
    const int i   = row & 1023;
    const int lo  = i - 7;

    // load k_i into shared (2 floats per lane)
    {
        const float* kp = g_C + (size_t)(b * S_ + i) * CN + h * HD_;
        float2 kv = *(const float2*)(kp + 2 * l);
        sk[wid][2 * l]     = kv.x;
        sk[wid][2 * l + 1] = kv.y;
    }
    __syncwarp();

    // lanes 0..14: one window position each
    float score = -FLT_MAX;
    if (l < 15) {
        const int j = lo + l;
        if (j >= 0 && j < S_ && mask[b * S_ + j] != 0) {
            const float* q = g_C + (size_t)(b * S_ + j) * CN + 1024 + h * HD_;
            float dot = 0.0f;
#pragma unroll
            for (int d = 0; d < HD_; d += 4) {
                float4 qq = *(const float4*)(q + d);
                dot += sk[wid][d]     * qq.x + sk[wid][d + 1] * qq.y
                     + sk[wid][d + 2] * qq.z + sk[wid][d + 3] * qq.w;
            }
            score = dot * 0.125f;
        }
    }

    // warp softmax over the window
    float m = score;
#pragma unroll
    for (int o = 16; o; o >>= 1) m = fmaxf(m, __shfl_xor_sync(0xFFFFFFFFu, m, o));
    const bool uniform = (m == -FLT_MAX);   // every window key masked/out-of-range

    float w = 0.0f;
    if (!uniform) {
        float e = (score != -FLT_MAX) ? expf(score - m) : 0.0f;
        float s = e;
#pragma unroll
        for (int o = 16; o; o >>= 1) s += __shfl_xor_sync(0xFFFFFFFFu, s, o);
        w = e / s;
    }
    if (l < 16) sw[wid][l] = (l < 15) ? w : 0.0f;
    __syncwarp();

    // r = sum_j w_j * v_j  (2 dims per lane)
    float r0 = 0.0f, r1 = 0.0f;
    if (!uniform) {
#pragma unroll
        for (int jj = 0; jj < 15; ++jj) {
            const float wv = sw[wid][jj];
            if (wv != 0.0f) {
                const float* v = g_C + (size_t)(b * S_ + lo + jj) * CN + 2048 + h * HD_;
                float2 vv = *(const float2*)(v + 2 * l);
                r0 = fmaf(wv, vv.x, r0);
                r1 = fmaf(wv, vv.y, r1);
            }
        }
    } else {
        const int c = h * HD_ + 2 * l;
        float s0 = 0.0f, s1 = 0.0f;
#pragma unroll
        for (int p = 0; p < 4; ++p) {
            s0 += g_vsum[p * (B_ * ODIM) + b * ODIM + c];
            s1 += g_vsum[p * (B_ * ODIM) + b * ODIM + c + 1];
        }
        r0 = s0 * (1.0f / 1024.0f);
        r1 = s1 * (1.0f / 1024.0f);
    }

    // updated_m = m_feats + r
    {
        const size_t uoff = (size_t)(b * S_ + i) * ODIM + h * HD_ + 2 * l;
        float2 mf = *(const float2*)(m_feats + uoff);
        float2 o;
        o.x = mf.x + r0;
        o.y = mf.y + r1;
        *(float2*)(out_um + uoff) = o;
    }

    // dense w row: 1024 floats, zeros outside the window (or uniform 1/1024)
    {
        float* wr = out_w + (size_t)row * S_;
        const float uval = 1.0f / 1024.0f;
#pragma unroll
        for (int tt = 0; tt < 8; ++tt) {
            const int col = tt * 128 + l * 4;
            float4 o;
            if (uniform) {
                o = make_float4(uval, uval, uval, uval);
            } else {
                o.x = ((unsigned)(col     - lo) < 15u) ? sw[wid][col     - lo] : 0.0f;
                o.y = ((unsigned)(col + 1 - lo) < 15u) ? sw[wid][col + 1 - lo] : 0.0f;
                o.z = ((unsigned)(col + 2 - lo) < 15u) ? sw[wid][col + 2 - lo] : 0.0f;
                o.w = ((unsigned)(col + 3 - lo) < 15u) ? sw[wid][col + 3 - lo] : 0.0f;
            }
            *(float4*)(wr + col) = o;
        }
    }
}

// ---------------------------------------------------------------------------
extern "C" void kernel_launch(void* const* d_in, const int* in_sizes, int n_in,
                              void* d_out, int out_size)
{
    (void)in_sizes; (void)n_in; (void)out_size;
    const float* m_feats = (const float*)d_in[0];
    const int*   mask    = (const int*)  d_in[1];
    const float* Wc      = (const float*)d_in[2];
    const float* bc      = (const float*)d_in[3];
    const float* Wv      = (const float*)d_in[4];
    const float* bv      = (const float*)d_in[5];

    float* out_um = (float*)d_out;                                   // (B,S,ODIM)
    float* out_w  = out_um + (size_t)B_ * S_ * ODIM;                 // (B,H,S,S)

    gemm_kernel<<<dim3(24, 64), 256>>>(m_feats, Wc, bc, Wv, bv);
    vsum_kernel<<<dim3(64, 4), 128>>>();
    attn_kernel<<<(B_ * H_ * S_) / 8, 256>>>(m_feats, mask, out_um, out_w);
}

// round 4
// speedup vs baseline: 1.4842x; 1.4842x over previous
#include <cuda_runtime.h>
#include <cuda_bf16.h>
#include <math.h>
#include <float.h>
#include <stdint.h>

// Problem constants
#define B_   8
#define S_   1024
#define IDIM 1024
#define ODIM 1024
#define H_   16
#define HD_  64
#define CN   3072           // K | Q | V columns in scratch
#define M_   (B_ * S_)      // 8192

// GEMM tiling
#define TM 128
#define TN 128
#define TK 32               // real-K per tile
#define NKT 32              // 1024 / 32
#define STAGE_BYTES 32768   // Ahi8K + Alo8K + Bhi8K + Blo8K
#define NSTAGE 3
#define SMEM_ALLOC (NSTAGE * STAGE_BYTES + 1024)

// Scratch
__device__ float g_C[(size_t)M_ * CN];               // K|Q|V fp32
__device__ float g_vsum[4 * B_ * ODIM];
__device__ float g_bias[CN];
__device__ __nv_bfloat16 g_Xhi[(size_t)M_ * IDIM];
__device__ __nv_bfloat16 g_Xlo[(size_t)M_ * IDIM];
__device__ __nv_bfloat16 g_Wthi[(size_t)CN * IDIM];  // W^T, [n][k] K-major
__device__ __nv_bfloat16 g_Wtlo[(size_t)CN * IDIM];

__device__ __forceinline__ uint32_t smem_u32(const void* p) {
    uint32_t a;
    asm("{ .reg .u64 t; cvta.to.shared.u64 t, %1; cvt.u32.u64 %0, t; }" : "=r"(a) : "l"(p));
    return a;
}
#define CP16(dst, src) \
    asm volatile("cp.async.cg.shared.global [%0], [%1], 16;" :: "r"(dst), "l"(src) : "memory")
#define CP_COMMIT() asm volatile("cp.async.commit_group;" ::: "memory")
#define CP_WAIT1()  asm volatile("cp.async.wait_group 1;" ::: "memory")

#define LDM4(r, addr) \
    asm volatile("ldmatrix.sync.aligned.m8n8.x4.shared.b16 {%0,%1,%2,%3}, [%4];" \
        : "=r"((r)[0]), "=r"((r)[1]), "=r"((r)[2]), "=r"((r)[3]) : "r"(addr))

#define MMA(acc, a, b0, b1) \
    asm volatile("mma.sync.aligned.m16n8k16.row.col.f32.bf16.bf16.f32 " \
        "{%0,%1,%2,%3}, {%4,%5,%6,%7}, {%8,%9}, {%0,%1,%2,%3};" \
        : "+f"((acc)[0]), "+f"((acc)[1]), "+f"((acc)[2]), "+f"((acc)[3]) \
        : "r"((a)[0]), "r"((a)[1]), "r"((a)[2]), "r"((a)[3]), "r"(b0), "r"(b1))

// ---------------------------------------------------------------------------
// xsplit: X -> bf16 hi/lo; also build combined bias
// ---------------------------------------------------------------------------
__global__ void xsplit_kernel(const float* __restrict__ X,
                              const float* __restrict__ bc, const float* __restrict__ bv)
{
    const size_t gid = (size_t)blockIdx.x * 256 + threadIdx.x;
    if (gid < CN) g_bias[gid] = (gid < 1024) ? bv[gid] : bc[gid - 1024];

    const size_t i = gid * 4;
    float4 x = *(const float4*)(X + i);
    float v[4] = { x.x, x.y, x.z, x.w };
    ushort4 uh, ul;
    unsigned short* ph = (unsigned short*)&uh;
    unsigned short* pl = (unsigned short*)&ul;
#pragma unroll
    for (int c = 0; c < 4; ++c) {
        __nv_bfloat16 h = __float2bfloat16(v[c]);
        __nv_bfloat16 l = __float2bfloat16(v[c] - __bfloat162float(h));
        ph[c] = __bfloat16_as_ushort(h);
        pl[c] = __bfloat16_as_ushort(l);
    }
    *reinterpret_cast<ushort4*>(g_Xhi + i) = uh;
    *reinterpret_cast<ushort4*>(g_Xlo + i) = ul;
}

// ---------------------------------------------------------------------------
// wtrans: W^T ([3072][1024] K-major) bf16 hi/lo.  cols 0..1023 = Wv, rest = Wc
// ---------------------------------------------------------------------------
__global__ void wtrans_kernel(const float* __restrict__ Wc, const float* __restrict__ Wv)
{
    __shared__ float tile[32][33];
    const int tx = threadIdx.x & 31;
    const int ty = threadIdx.x >> 5;
    const int nb = blockIdx.x * 32;
    const int kb = blockIdx.y * 32;

#pragma unroll
    for (int p = 0; p < 4; ++p) {
        const int k = kb + p * 8 + ty;
        const int n = nb + tx;
        float v = (n < 1024) ? Wv[(size_t)k * 1024 + n]
                             : Wc[(size_t)k * 2048 + (n - 1024)];
        tile[tx][p * 8 + ty] = v;
    }
    __syncthreads();
#pragma unroll
    for (int p = 0; p < 4; ++p) {
        const int nl = p * 8 + ty;
        float v = tile[nl][tx];
        __nv_bfloat16 h = __float2bfloat16(v);
        __nv_bfloat16 l = __float2bfloat16(v - __bfloat162float(h));
        const size_t o = (size_t)(nb + nl) * 1024 + kb + tx;
        g_Wthi[o] = h;
        g_Wtlo[o] = l;
    }
}

// ---------------------------------------------------------------------------
// HMMA split-bf16 GEMM: C[8192 x 3072] = X @ W + bias  (3-pass Markidis)
// 128x128 CTA tile, 8 warps (2m x 4n), warp tile 64x32, k-tile 32, 3 stages
// Smem tile layout: row-major 32 bf16 (64B = 4 x 16B chunks), chunk swizzle
// chunk' = chunk ^ ((row>>1)&3)  -> conflict-free ldmatrix + cp.async
// ---------------------------------------------------------------------------
__global__ void __launch_bounds__(256, 1) mma_kernel()
{
    extern __shared__ __align__(16) char smem[];
    const uint32_t sb0 = smem_u32(smem);
    const uint32_t db  = (sb0 + 1023) & ~1023u;

    const int t  = threadIdx.x;
    const int l  = t & 31;
    const int w  = t >> 5;
    const int wm = w >> 2;          // 0..1
    const int wn = w & 3;           // 0..3
    const int n0 = blockIdx.x * TN;
    const int m0 = blockIdx.y * TM;

    // ---- cp.async stage loader ----
    const int lrow = t >> 1;               // 0..127
    const int lc0  = (t & 1) * 2;          // chunk 0 or 2
    const int lsw  = (lrow >> 1) & 3;
    auto load_stage = [&](int kt, int s) {
        const uint32_t sbase = db + s * STAGE_BYTES;
        const size_t gA = (size_t)(m0 + lrow) * 1024 + kt * TK;
        const size_t gB = (size_t)(n0 + lrow) * 1024 + kt * TK;
#pragma unroll
        for (int cc = 0; cc < 2; ++cc) {
            const int ch = lc0 + cc;
            const uint32_t so = (uint32_t)(lrow * 64 + ((ch ^ lsw) << 4));
            CP16(sbase + so,         g_Xhi  + gA + ch * 8);
            CP16(sbase + 8192 + so,  g_Xlo  + gA + ch * 8);
            CP16(sbase + 16384 + so, g_Wthi + gB + ch * 8);
            CP16(sbase + 24576 + so, g_Wtlo + gB + ch * 8);
        }
    };

    // ---- per-thread ldmatrix address invariants ----
    // A: row = wm*64 + mt*16 + (l & 15); chunk-hi bit = (l>>4)&1
    uint32_t offA[4], swA[4];
#pragma unroll
    for (int mt = 0; mt < 4; ++mt) {
        const int r = wm * 64 + mt * 16 + (l & 15);
        offA[mt] = (uint32_t)(r * 64);
        swA[mt]  = (uint32_t)(((r >> 1) & 3) << 4);
    }
    const uint32_t ahib = ((l >> 4) & 1) << 4;
    // B: row = wn*32 + nt2*16 + (l&7) + ((l&16)?8:0); chunk-hi bit = (l>>3)&1
    uint32_t offB[2], swB[2];
#pragma unroll
    for (int nt2 = 0; nt2 < 2; ++nt2) {
        const int r = wn * 32 + nt2 * 16 + (l & 7) + ((l & 16) ? 8 : 0);
        offB[nt2] = (uint32_t)(r * 64);
        swB[nt2]  = (uint32_t)(((r >> 1) & 3) << 4);
    }
    const uint32_t bhib = ((l >> 3) & 1) << 4;

    float acc[4][4][4];
#pragma unroll
    for (int mt = 0; mt < 4; ++mt)
#pragma unroll
        for (int nt = 0; nt < 4; ++nt)
#pragma unroll
            for (int c = 0; c < 4; ++c) acc[mt][nt][c] = 0.0f;

    // ---- pipeline ----
    load_stage(0, 0); CP_COMMIT();
    load_stage(1, 1); CP_COMMIT();

    for (int kt = 0; kt < NKT; ++kt) {
        CP_WAIT1();
        __syncthreads();
        if (kt + 2 < NKT) load_stage(kt + 2, (kt + 2) % NSTAGE);
        CP_COMMIT();

        const uint32_t sbase = db + (kt % NSTAGE) * STAGE_BYTES;
#pragma unroll
        for (int ks = 0; ks < 2; ++ks) {
            const uint32_t kchA = (uint32_t)(ks * 32) + ahib;   // chunk*16
            const uint32_t kchB = (uint32_t)(ks * 32) + bhib;
            uint32_t ahi[4][4], alo[4][4], bhi[2][4], blo[2][4];
#pragma unroll
            for (int mt = 0; mt < 4; ++mt) {
                const uint32_t ad = sbase + offA[mt] + (kchA ^ swA[mt]);
                LDM4(ahi[mt], ad);
                LDM4(alo[mt], ad + 8192);
            }
#pragma unroll
            for (int nt2 = 0; nt2 < 2; ++nt2) {
                const uint32_t bd = sbase + 16384 + offB[nt2] + (kchB ^ swB[nt2]);
                LDM4(bhi[nt2], bd);
                LDM4(blo[nt2], bd + 8192);
            }
#pragma unroll
            for (int mt = 0; mt < 4; ++mt)
#pragma unroll
                for (int nt = 0; nt < 4; ++nt) {
                    const int q = nt >> 1, h = (nt & 1) * 2;
                    MMA(acc[mt][nt], ahi[mt], bhi[q][h], bhi[q][h + 1]);
                    MMA(acc[mt][nt], ahi[mt], blo[q][h], blo[q][h + 1]);
                    MMA(acc[mt][nt], alo[mt], bhi[q][h], bhi[q][h + 1]);
                }
        }
    }

    // ---- epilogue: bias + fp32 store to g_C ----
#pragma unroll
    for (int mt = 0; mt < 4; ++mt) {
        const int r0 = m0 + wm * 64 + mt * 16 + (l >> 2);
#pragma unroll
        for (int nt = 0; nt < 4; ++nt) {
            const int col = n0 + wn * 32 + nt * 8 + (l & 3) * 2;
            const float2 bb = *(const float2*)(g_bias + col);
            float2 o;
            o.x = acc[mt][nt][0] + bb.x;
            o.y = acc[mt][nt][1] + bb.y;
            *(float2*)(g_C + (size_t)r0 * CN + col) = o;
            o.x = acc[mt][nt][2] + bb.x;
            o.y = acc[mt][nt][3] + bb.y;
            *(float2*)(g_C + (size_t)(r0 + 8) * CN + col) = o;
        }
    }
}

// ---------------------------------------------------------------------------
// Partial column sums of V (uniform fallback)
// ---------------------------------------------------------------------------
__global__ void vsum_kernel()
{
    const int col = (blockIdx.x & 7) * 128 + threadIdx.x;
    const int b   = blockIdx.x >> 3;
    const int s0  = blockIdx.y * 256;
    const float* base = g_C + (size_t)(b * S_ + s0) * CN + 2048 + col;
    float s = 0.0f;
#pragma unroll 8
    for (int k = 0; k < 256; ++k) s += base[(size_t)k * CN];
    g_vsum[blockIdx.y * (B_ * ODIM) + b * ODIM + col] = s;
}

// ---------------------------------------------------------------------------
// Local attention (one warp per row) — unchanged (passed R2)
// ---------------------------------------------------------------------------
__global__ void __launch_bounds__(256) attn_kernel(
    const float* __restrict__ m_feats, const int* __restrict__ mask,
    float* __restrict__ out_um, float* __restrict__ out_w)
{
    __shared__ float sk[8][64];
    __shared__ float sw[8][16];

    const int wid = threadIdx.x >> 5;
    const int l   = threadIdx.x & 31;
    const int row = blockIdx.x * 8 + wid;
    const int b   = row >> 14;
    const int h   = (row >> 10) & 15;
    const int i   = row & 1023;
    const int lo  = i - 7;

    {
        const float* kp = g_C + (size_t)(b * S_ + i) * CN + h * HD_;
        float2 kv = *(const float2*)(kp + 2 * l);
        sk[wid][2 * l]     = kv.x;
        sk[wid][2 * l + 1] = kv.y;
    }
    __syncwarp();

    float score = -FLT_MAX;
    if (l < 15) {
        const int j = lo + l;
        if (j >= 0 && j < S_ && mask[b * S_ + j] != 0) {
            const float* q = g_C + (size_t)(b * S_ + j) * CN + 1024 + h * HD_;
            float dot = 0.0f;
#pragma unroll
            for (int d = 0; d < HD_; d += 4) {
                float4 qq = *(const float4*)(q + d);
                dot += sk[wid][d]     * qq.x + sk[wid][d + 1] * qq.y
                     + sk[wid][d + 2] * qq.z + sk[wid][d + 3] * qq.w;
            }
            score = dot * 0.125f;
        }
    }

    float m = score;
#pragma unroll
    for (int o = 16; o; o >>= 1) m = fmaxf(m, __shfl_xor_sync(0xFFFFFFFFu, m, o));
    const bool uniform = (m == -FLT_MAX);

    float w = 0.0f;
    if (!uniform) {
        float e = (score != -FLT_MAX) ? expf(score - m) : 0.0f;
        float s = e;
#pragma unroll
        for (int o = 16; o; o >>= 1) s += __shfl_xor_sync(0xFFFFFFFFu, s, o);
        w = e / s;
    }
    if (l < 16) sw[wid][l] = (l < 15) ? w : 0.0f;
    __syncwarp();

    float r0 = 0.0f, r1 = 0.0f;
    if (!uniform) {
#pragma unroll
        for (int jj = 0; jj < 15; ++jj) {
            const float wv = sw[wid][jj];
            if (wv != 0.0f) {
                const float* v = g_C + (size_t)(b * S_ + lo + jj) * CN + 2048 + h * HD_;
                float2 vv = *(const float2*)(v + 2 * l);
                r0 = fmaf(wv, vv.x, r0);
                r1 = fmaf(wv, vv.y, r1);
            }
        }
    } else {
        const int c = h * HD_ + 2 * l;
        float s0 = 0.0f, s1 = 0.0f;
#pragma unroll
        for (int p = 0; p < 4; ++p) {
            s0 += g_vsum[p * (B_ * ODIM) + b * ODIM + c];
            s1 += g_vsum[p * (B_ * ODIM) + b * ODIM + c + 1];
        }
        r0 = s0 * (1.0f / 1024.0f);
        r1 = s1 * (1.0f / 1024.0f);
    }

    {
        const size_t uoff = (size_t)(b * S_ + i) * ODIM + h * HD_ + 2 * l;
        float2 mf = *(const float2*)(m_feats + uoff);
        float2 o;
        o.x = mf.x + r0;
        o.y = mf.y + r1;
        *(float2*)(out_um + uoff) = o;
    }

    {
        float* wr = out_w + (size_t)row * S_;
        const float uval = 1.0f / 1024.0f;
#pragma unroll
        for (int tt = 0; tt < 8; ++tt) {
            const int col = tt * 128 + l * 4;
            float4 o;
            if (uniform) {
                o = make_float4(uval, uval, uval, uval);
            } else {
                o.x = ((unsigned)(col     - lo) < 15u) ? sw[wid][col     - lo] : 0.0f;
                o.y = ((unsigned)(col + 1 - lo) < 15u) ? sw[wid][col + 1 - lo] : 0.0f;
                o.z = ((unsigned)(col + 2 - lo) < 15u) ? sw[wid][col + 2 - lo] : 0.0f;
                o.w = ((unsigned)(col + 3 - lo) < 15u) ? sw[wid][col + 3 - lo] : 0.0f;
            }
            *(float4*)(wr + col) = o;
        }
    }
}

// ---------------------------------------------------------------------------
extern "C" void kernel_launch(void* const* d_in, const int* in_sizes, int n_in,
                              void* d_out, int out_size)
{
    (void)in_sizes; (void)n_in; (void)out_size;
    const float* m_feats = (const float*)d_in[0];
    const int*   mask    = (const int*)  d_in[1];
    const float* Wc      = (const float*)d_in[2];
    const float* bc      = (const float*)d_in[3];
    const float* Wv      = (const float*)d_in[4];
    const float* bv      = (const float*)d_in[5];

    float* out_um = (float*)d_out;
    float* out_w  = out_um + (size_t)B_ * S_ * ODIM;

    cudaFuncSetAttribute(mma_kernel, cudaFuncAttributeMaxDynamicSharedMemorySize, SMEM_ALLOC);

    xsplit_kernel<<<(M_ * IDIM) / 1024, 256>>>(m_feats, bc, bv);
    wtrans_kernel<<<dim3(CN / 32, IDIM / 32), 256>>>(Wc, Wv);
    mma_kernel<<<dim3(CN / TN, M_ / TM), 256, SMEM_ALLOC>>>();
    vsum_kernel<<<dim3(64, 4), 128>>>();
    attn_kernel<<<(B_ * H_ * S_) / 8, 256>>>(m_feats, mask, out_um, out_w);
}

// round 5
// speedup vs baseline: 1.6604x; 1.1187x over previous
#include <cuda_runtime.h>
#include <cuda_bf16.h>
#include <math.h>
#include <float.h>
#include <stdint.h>

// Problem constants
#define B_   8
#define S_   1024
#define IDIM 1024
#define ODIM 1024
#define H_   16
#define HD_  64
#define CN   3072           // K | Q | V columns in scratch
#define M_   (B_ * S_)      // 8192

// GEMM tiling
#define TM 128
#define TN 128
#define TK 32               // real-K per tile
#define NKT 32              // 1024 / 32
#define STAGE_BYTES 32768   // Ahi8K + Alo8K + Bhi8K + Blo8K
#define SMEM_ALLOC (2 * STAGE_BYTES + 1024)

// Scratch
__device__ float g_C[(size_t)M_ * CN];               // K|Q|V fp32
__device__ float g_vsum[4 * B_ * ODIM];
__device__ float g_bias[CN];
__device__ __nv_bfloat16 g_Xhi[(size_t)M_ * IDIM];
__device__ __nv_bfloat16 g_Xlo[(size_t)M_ * IDIM];
__device__ __nv_bfloat16 g_Wthi[(size_t)CN * IDIM];  // W^T, [n][k] K-major
__device__ __nv_bfloat16 g_Wtlo[(size_t)CN * IDIM];

__device__ __forceinline__ uint32_t smem_u32(const void* p) {
    uint32_t a;
    asm("{ .reg .u64 t; cvta.to.shared.u64 t, %1; cvt.u32.u64 %0, t; }" : "=r"(a) : "l"(p));
    return a;
}
#define CP16(dst, src) \
    asm volatile("cp.async.cg.shared.global [%0], [%1], 16;" :: "r"(dst), "l"(src) : "memory")
#define CP_COMMIT() asm volatile("cp.async.commit_group;" ::: "memory")
#define CP_WAIT1()  asm volatile("cp.async.wait_group 1;" ::: "memory")
#define CP_WAIT0()  asm volatile("cp.async.wait_group 0;" ::: "memory")

#define LDM4(r, addr) \
    asm volatile("ldmatrix.sync.aligned.m8n8.x4.shared.b16 {%0,%1,%2,%3}, [%4];" \
        : "=r"((r)[0]), "=r"((r)[1]), "=r"((r)[2]), "=r"((r)[3]) : "r"(addr))

#define MMA(acc, a, b0, b1) \
    asm volatile("mma.sync.aligned.m16n8k16.row.col.f32.bf16.bf16.f32 " \
        "{%0,%1,%2,%3}, {%4,%5,%6,%7}, {%8,%9}, {%0,%1,%2,%3};" \
        : "+f"((acc)[0]), "+f"((acc)[1]), "+f"((acc)[2]), "+f"((acc)[3]) \
        : "r"((a)[0]), "r"((a)[1]), "r"((a)[2]), "r"((a)[3]), "r"(b0), "r"(b1))

// ---------------------------------------------------------------------------
// xsplit: X -> bf16 hi/lo; also build combined bias
// ---------------------------------------------------------------------------
__global__ void xsplit_kernel(const float* __restrict__ X,
                              const float* __restrict__ bc, const float* __restrict__ bv)
{
    const size_t gid = (size_t)blockIdx.x * 256 + threadIdx.x;
    if (gid < CN) g_bias[gid] = (gid < 1024) ? bv[gid] : bc[gid - 1024];

    const size_t i = gid * 4;
    float4 x = *(const float4*)(X + i);
    float v[4] = { x.x, x.y, x.z, x.w };
    ushort4 uh, ul;
    unsigned short* ph = (unsigned short*)&uh;
    unsigned short* pl = (unsigned short*)&ul;
#pragma unroll
    for (int c = 0; c < 4; ++c) {
        __nv_bfloat16 h = __float2bfloat16(v[c]);
        __nv_bfloat16 l = __float2bfloat16(v[c] - __bfloat162float(h));
        ph[c] = __bfloat16_as_ushort(h);
        pl[c] = __bfloat16_as_ushort(l);
    }
    *reinterpret_cast<ushort4*>(g_Xhi + i) = uh;
    *reinterpret_cast<ushort4*>(g_Xlo + i) = ul;
}

// ---------------------------------------------------------------------------
// wtrans: W^T ([3072][1024] K-major) bf16 hi/lo.  cols 0..1023 = Wv, rest = Wc
// ---------------------------------------------------------------------------
__global__ void wtrans_kernel(const float* __restrict__ Wc, const float* __restrict__ Wv)
{
    __shared__ float tile[32][33];
    const int tx = threadIdx.x & 31;
    const int ty = threadIdx.x >> 5;
    const int nb = blockIdx.x * 32;
    const int kb = blockIdx.y * 32;

#pragma unroll
    for (int p = 0; p < 4; ++p) {
        const int k = kb + p * 8 + ty;
        const int n = nb + tx;
        float v = (n < 1024) ? Wv[(size_t)k * 1024 + n]
                             : Wc[(size_t)k * 2048 + (n - 1024)];
        tile[tx][p * 8 + ty] = v;
    }
    __syncthreads();
#pragma unroll
    for (int p = 0; p < 4; ++p) {
        const int nl = p * 8 + ty;
        float v = tile[nl][tx];
        __nv_bfloat16 h = __float2bfloat16(v);
        __nv_bfloat16 l = __float2bfloat16(v - __bfloat162float(h));
        const size_t o = (size_t)(nb + nl) * 1024 + kb + tx;
        g_Wthi[o] = h;
        g_Wtlo[o] = l;
    }
}

// ---------------------------------------------------------------------------
// HMMA split-bf16 GEMM: C[8192 x 3072] = X @ W + bias  (3-pass Markidis)
// 128x128 CTA tile, 8 warps (2m x 4n), warp tile 64x32, k-tile 32
// 2-stage cp.async pipeline, 2 CTAs/SM.
// Smem tile layout: row-major 32 bf16 (64B = 4 x 16B chunks), chunk swizzle
// chunk' = chunk ^ ((row>>1)&3)  -> conflict-free ldmatrix + cp.async
// ---------------------------------------------------------------------------
__global__ void __launch_bounds__(256, 2) mma_kernel()
{
    extern __shared__ __align__(16) char smem[];
    const uint32_t sb0 = smem_u32(smem);
    const uint32_t db  = (sb0 + 1023) & ~1023u;

    const int t  = threadIdx.x;
    const int l  = t & 31;
    const int w  = t >> 5;
    const int wm = w >> 2;          // 0..1
    const int wn = w & 3;           // 0..3
    const int n0 = blockIdx.x * TN;
    const int m0 = blockIdx.y * TM;

    // ---- cp.async stage loader ----
    const int lrow = t >> 1;               // 0..127
    const int lc0  = (t & 1) * 2;          // chunk 0 or 2
    const int lsw  = (lrow >> 1) & 3;
    auto load_stage = [&](int kt, int s) {
        const uint32_t sbase = db + s * STAGE_BYTES;
        const size_t gA = (size_t)(m0 + lrow) * 1024 + kt * TK;
        const size_t gB = (size_t)(n0 + lrow) * 1024 + kt * TK;
#pragma unroll
        for (int cc = 0; cc < 2; ++cc) {
            const int ch = lc0 + cc;
            const uint32_t so = (uint32_t)(lrow * 64 + ((ch ^ lsw) << 4));
            CP16(sbase + so,         g_Xhi  + gA + ch * 8);
            CP16(sbase + 8192 + so,  g_Xlo  + gA + ch * 8);
            CP16(sbase + 16384 + so, g_Wthi + gB + ch * 8);
            CP16(sbase + 24576 + so, g_Wtlo + gB + ch * 8);
        }
    };

    // ---- per-thread ldmatrix address invariants ----
    uint32_t offA[4], swA[4];
#pragma unroll
    for (int mt = 0; mt < 4; ++mt) {
        const int r = wm * 64 + mt * 16 + (l & 15);
        offA[mt] = (uint32_t)(r * 64);
        swA[mt]  = (uint32_t)(((r >> 1) & 3) << 4);
    }
    const uint32_t ahib = ((l >> 4) & 1) << 4;
    uint32_t offB[2], swB[2];
#pragma unroll
    for (int nt2 = 0; nt2 < 2; ++nt2) {
        const int r = wn * 32 + nt2 * 16 + (l & 7) + ((l & 16) ? 8 : 0);
        offB[nt2] = (uint32_t)(r * 64);
        swB[nt2]  = (uint32_t)(((r >> 1) & 3) << 4);
    }
    const uint32_t bhib = ((l >> 3) & 1) << 4;

    float acc[4][4][4];
#pragma unroll
    for (int mt = 0; mt < 4; ++mt)
#pragma unroll
        for (int nt = 0; nt < 4; ++nt)
#pragma unroll
            for (int c = 0; c < 4; ++c) acc[mt][nt][c] = 0.0f;

    // ---- 2-stage pipeline ----
    load_stage(0, 0); CP_COMMIT();

    for (int kt = 0; kt < NKT; ++kt) {
        if (kt + 1 < NKT) {
            load_stage(kt + 1, (kt + 1) & 1);
            CP_COMMIT();
            CP_WAIT1();
        } else {
            CP_WAIT0();
        }
        __syncthreads();

        const uint32_t sbase = db + (kt & 1) * STAGE_BYTES;
#pragma unroll
        for (int ks = 0; ks < 2; ++ks) {
            const uint32_t kchA = (uint32_t)(ks * 32) + ahib;   // chunk*16
            const uint32_t kchB = (uint32_t)(ks * 32) + bhib;
            uint32_t bhi[2][4], blo[2][4], a[4][4];
#pragma unroll
            for (int nt2 = 0; nt2 < 2; ++nt2) {
                const uint32_t bd = sbase + 16384 + offB[nt2] + (kchB ^ swB[nt2]);
                LDM4(bhi[nt2], bd);
                LDM4(blo[nt2], bd + 8192);
            }
            // pass 1+2: A-hi x (B-hi, B-lo)
#pragma unroll
            for (int mt = 0; mt < 4; ++mt)
                LDM4(a[mt], sbase + offA[mt] + (kchA ^ swA[mt]));
#pragma unroll
            for (int mt = 0; mt < 4; ++mt)
#pragma unroll
                for (int nt = 0; nt < 4; ++nt) {
                    const int q = nt >> 1, hh = (nt & 1) * 2;
                    MMA(acc[mt][nt], a[mt], bhi[q][hh], bhi[q][hh + 1]);
                    MMA(acc[mt][nt], a[mt], blo[q][hh], blo[q][hh + 1]);
                }
            // pass 3: A-lo x B-hi (overwrites A frags)
#pragma unroll
            for (int mt = 0; mt < 4; ++mt)
                LDM4(a[mt], sbase + 8192 + offA[mt] + (kchA ^ swA[mt]));
#pragma unroll
            for (int mt = 0; mt < 4; ++mt)
#pragma unroll
                for (int nt = 0; nt < 4; ++nt) {
                    const int q = nt >> 1, hh = (nt & 1) * 2;
                    MMA(acc[mt][nt], a[mt], bhi[q][hh], bhi[q][hh + 1]);
                }
        }
        __syncthreads();
    }

    // ---- epilogue: bias + fp32 store to g_C ----
#pragma unroll
    for (int mt = 0; mt < 4; ++mt) {
        const int r0 = m0 + wm * 64 + mt * 16 + (l >> 2);
#pragma unroll
        for (int nt = 0; nt < 4; ++nt) {
            const int col = n0 + wn * 32 + nt * 8 + (l & 3) * 2;
            const float2 bb = *(const float2*)(g_bias + col);
            float2 o;
            o.x = acc[mt][nt][0] + bb.x;
            o.y = acc[mt][nt][1] + bb.y;
            *(float2*)(g_C + (size_t)r0 * CN + col) = o;
            o.x = acc[mt][nt][2] + bb.x;
            o.y = acc[mt][nt][3] + bb.y;
            *(float2*)(g_C + (size_t)(r0 + 8) * CN + col) = o;
        }
    }
}

// ---------------------------------------------------------------------------
// Partial column sums of V (uniform fallback)
// ---------------------------------------------------------------------------
__global__ void vsum_kernel()
{
    const int col = (blockIdx.x & 7) * 128 + threadIdx.x;
    const int b   = blockIdx.x >> 3;
    const int s0  = blockIdx.y * 256;
    const float* base = g_C + (size_t)(b * S_ + s0) * CN + 2048 + col;
    float s = 0.0f;
#pragma unroll 8
    for (int k = 0; k < 256; ++k) s += base[(size_t)k * CN];
    g_vsum[blockIdx.y * (B_ * ODIM) + b * ODIM + col] = s;
}

// ---------------------------------------------------------------------------
// Local attention (one warp per row) — unchanged (passed R2/R4)
// ---------------------------------------------------------------------------
__global__ void __launch_bounds__(256) attn_kernel(
    const float* __restrict__ m_feats, const int* __restrict__ mask,
    float* __restrict__ out_um, float* __restrict__ out_w)
{
    __shared__ float sk[8][64];
    __shared__ float sw[8][16];

    const int wid = threadIdx.x >> 5;
    const int l   = threadIdx.x & 31;
    const int row = blockIdx.x * 8 + wid;
    const int b   = row >> 14;
    const int h   = (row >> 10) & 15;
    const int i   = row & 1023;
    const int lo  = i - 7;

    {
        const float* kp = g_C + (size_t)(b * S_ + i) * CN + h * HD_;
        float2 kv = *(const float2*)(kp + 2 * l);
        sk[wid][2 * l]     = kv.x;
        sk[wid][2 * l + 1] = kv.y;
    }
    __syncwarp();

    float score = -FLT_MAX;
    if (l < 15) {
        const int j = lo + l;
        if (j >= 0 && j < S_ && mask[b * S_ + j] != 0) {
            const float* q = g_C + (size_t)(b * S_ + j) * CN + 1024 + h * HD_;
            float dot = 0.0f;
#pragma unroll
            for (int d = 0; d < HD_; d += 4) {
                float4 qq = *(const float4*)(q + d);
                dot += sk[wid][d]     * qq.x + sk[wid][d + 1] * qq.y
                     + sk[wid][d + 2] * qq.z + sk[wid][d + 3] * qq.w;
            }
            score = dot * 0.125f;
        }
    }

    float m = score;
#pragma unroll
    for (int o = 16; o; o >>= 1) m = fmaxf(m, __shfl_xor_sync(0xFFFFFFFFu, m, o));
    const bool uniform = (m == -FLT_MAX);

    float w = 0.0f;
    if (!uniform) {
        float e = (score != -FLT_MAX) ? expf(score - m) : 0.0f;
        float s = e;
#pragma unroll
        for (int o = 16; o; o >>= 1) s += __shfl_xor_sync(0xFFFFFFFFu, s, o);
        w = e / s;
    }
    if (l < 16) sw[wid][l] = (l < 15) ? w : 0.0f;
    __syncwarp();

    float r0 = 0.0f, r1 = 0.0f;
    if (!uniform) {
#pragma unroll
        for (int jj = 0; jj < 15; ++jj) {
            const float wv = sw[wid][jj];
            if (wv != 0.0f) {
                const float* v = g_C + (size_t)(b * S_ + lo + jj) * CN + 2048 + h * HD_;
                float2 vv = *(const float2*)(v + 2 * l);
                r0 = fmaf(wv, vv.x, r0);
                r1 = fmaf(wv, vv.y, r1);
            }
        }
    } else {
        const int c = h * HD_ + 2 * l;
        float s0 = 0.0f, s1 = 0.0f;
#pragma unroll
        for (int p = 0; p < 4; ++p) {
            s0 += g_vsum[p * (B_ * ODIM) + b * ODIM + c];
            s1 += g_vsum[p * (B_ * ODIM) + b * ODIM + c + 1];
        }
        r0 = s0 * (1.0f / 1024.0f);
        r1 = s1 * (1.0f / 1024.0f);
    }

    {
        const size_t uoff = (size_t)(b * S_ + i) * ODIM + h * HD_ + 2 * l;
        float2 mf = *(const float2*)(m_feats + uoff);
        float2 o;
        o.x = mf.x + r0;
        o.y = mf.y + r1;
        *(float2*)(out_um + uoff) = o;
    }

    {
        float* wr = out_w + (size_t)row * S_;
        const float uval = 1.0f / 1024.0f;
#pragma unroll
        for (int tt = 0; tt < 8; ++tt) {
            const int col = tt * 128 + l * 4;
            float4 o;
            if (uniform) {
                o = make_float4(uval, uval, uval, uval);
            } else {
                o.x = ((unsigned)(col     - lo) < 15u) ? sw[wid][col     - lo] : 0.0f;
                o.y = ((unsigned)(col + 1 - lo) < 15u) ? sw[wid][col + 1 - lo] : 0.0f;
                o.z = ((unsigned)(col + 2 - lo) < 15u) ? sw[wid][col + 2 - lo] : 0.0f;
                o.w = ((unsigned)(col + 3 - lo) < 15u) ? sw[wid][col + 3 - lo] : 0.0f;
            }
            *(float4*)(wr + col) = o;
        }
    }
}

// ---------------------------------------------------------------------------
extern "C" void kernel_launch(void* const* d_in, const int* in_sizes, int n_in,
                              void* d_out, int out_size)
{
    (void)in_sizes; (void)n_in; (void)out_size;
    const float* m_feats = (const float*)d_in[0];
    const int*   mask    = (const int*)  d_in[1];
    const float* Wc      = (const float*)d_in[2];
    const float* bc      = (const float*)d_in[3];
    const float* Wv      = (const float*)d_in[4];
    const float* bv      = (const float*)d_in[5];

    float* out_um = (float*)d_out;
    float* out_w  = out_um + (size_t)B_ * S_ * ODIM;

    cudaFuncSetAttribute(mma_kernel, cudaFuncAttributeMaxDynamicSharedMemorySize, SMEM_ALLOC);

    xsplit_kernel<<<(M_ * IDIM) / 1024, 256>>>(m_feats, bc, bv);
    wtrans_kernel<<<dim3(CN / 32, IDIM / 32), 256>>>(Wc, Wv);
    mma_kernel<<<dim3(CN / TN, M_ / TM), 256, SMEM_ALLOC>>>();
    vsum_kernel<<<dim3(64, 4), 128>>>();
    attn_kernel<<<(B_ * H_ * S_) / 8, 256>>>(m_feats, mask, out_um, out_w);
}